// round 2
// baseline (speedup 1.0000x reference)
#include <cuda_runtime.h>
#include <math.h>

#define Bn 8
#define Cn 2048
#define Dn 64
#define Hn 4
#define Ln 3
#define FFn 256
#define OUTn 10
#define BHn (Bn*Hn)

__device__ float g_h   [Bn*Cn*Dn];
__device__ float g_q   [Bn*Cn*Dn];
__device__ float g_k   [Bn*Cn*Dn];
__device__ float g_v   [Bn*Cn*Dn];
__device__ float g_qp  [Bn*Cn*Dn];
__device__ float g_kp  [Bn*Cn*Dn];
__device__ float g_attn[Bn*Cn*Dn];
__device__ float g_ff  [Bn*Cn*FFn];
__device__ float g_S   [(size_t)BHn*Cn*Cn];   // 512 MB score scratch

__device__ __forceinline__ float gelu_f(float v){
    return 0.5f*v*(1.0f + erff(v*0.70710678118654752f));
}

__global__ void k_binding(const float* __restrict__ x, const float* __restrict__ role,
                          const float* __restrict__ fw){
    int idx = blockIdx.x*blockDim.x + threadIdx.x;
    if (idx >= Bn*Cn*Dn) return;
    int dd = idx & 63;
    int bc = idx >> 6;
    int c  = bc & (Cn-1);
    float xl = log1pf(fmaxf(x[bc], 0.0f));
    g_h[idx] = role[c*Dn + dd] * gelu_f(xl * fw[dd]);
}

__global__ void k_qkv(const float* __restrict__ qw, const float* __restrict__ qb,
                      const float* __restrict__ kw, const float* __restrict__ kb,
                      const float* __restrict__ vw, const float* __restrict__ vb){
    __shared__ float hs[4][Dn];
    int r0 = blockIdx.x*4;
    int t  = threadIdx.x;
    for (int i=t; i<4*Dn; i+=64) hs[i>>6][i&63] = g_h[r0*Dn + i];
    __syncthreads();
    int o = t;
    float bq=qb[o], bk=kb[o], bv=vb[o];
    float aq[4]={bq,bq,bq,bq}, ak[4]={bk,bk,bk,bk}, av[4]={bv,bv,bv,bv};
    for (int d=0; d<Dn; d++){
        float wq=qw[o*Dn+d], wk2=kw[o*Dn+d], wv=vw[o*Dn+d];
        #pragma unroll
        for (int r=0;r<4;r++){
            float hh = hs[r][d];
            aq[r]=fmaf(wq ,hh,aq[r]);
            ak[r]=fmaf(wk2,hh,ak[r]);
            av[r]=fmaf(wv ,hh,av[r]);
        }
    }
    #pragma unroll
    for (int r=0;r<4;r++){
        g_q[(r0+r)*Dn+o]=aq[r];
        g_k[(r0+r)*Dn+o]=ak[r];
        g_v[(r0+r)*Dn+o]=av[r];
    }
}

__global__ void k_phead(const float* __restrict__ w1l){
    __shared__ float qs[4][Dn], ks[4][Dn];
    int r0 = blockIdx.x*4;
    int t  = threadIdx.x;
    for (int i=t;i<4*Dn;i+=64){ qs[i>>6][i&63]=g_q[r0*Dn+i]; ks[i>>6][i&63]=g_k[r0*Dn+i]; }
    __syncthreads();
    int o=t, hh=o>>4, ci=o&15;
    float wq[16], wk[16];
    #pragma unroll
    for (int e=0;e<16;e++){ wq[e]=w1l[ci*48+e]; wk[e]=w1l[ci*48+16+e]; }
    #pragma unroll
    for (int r=0;r<4;r++){
        float aq=0.f, ak=0.f;
        #pragma unroll
        for (int e=0;e<16;e++){
            aq = fmaf(qs[r][hh*16+e], wq[e], aq);
            ak = fmaf(ks[r][hh*16+e], wk[e], ak);
        }
        g_qp[(r0+r)*Dn+o]=aq;
        g_kp[(r0+r)*Dn+o]=ak;
    }
}

// hot loop: grid (C/32 j, C/32 i, B*H), 256 threads = 32 i x (8 groups x 4 j)
__global__ void __launch_bounds__(256) k_score(const float* __restrict__ w1l,
                                               const float* __restrict__ b1l,
                                               const float* __restrict__ w2l,
                                               const float* __restrict__ b2l){
    __shared__ float qs [32][17], ks [32][17];
    __shared__ float qps[32][17], kps[32][17];
    __shared__ float4 wqk4[16][4];
    __shared__ float b1s[16], w2s[16];

    int bh = blockIdx.z; int b = bh>>2; int hh = bh&3;
    int i0 = blockIdx.y<<5, j0 = blockIdx.x<<5;
    int t  = threadIdx.x;

    for (int idx=t; idx<512; idx+=256){
        int row=idx>>4, e=idx&15;
        int gq = (b*Cn + i0+row)*Dn + hh*16 + e;
        int gk = (b*Cn + j0+row)*Dn + hh*16 + e;
        qs [row][e]=g_q [gq];  qps[row][e]=g_qp[gq];
        ks [row][e]=g_k [gk];  kps[row][e]=g_kp[gk];
    }
    if (t<64){
        int ci=t>>2, qd=t&3;
        wqk4[ci][qd] = make_float4(w1l[ci*48+32+qd*4+0], w1l[ci*48+32+qd*4+1],
                                   w1l[ci*48+32+qd*4+2], w1l[ci*48+32+qd*4+3]);
    }
    if (t<16){ b1s[t]=b1l[t]; w2s[t]=w2l[t]; }
    __syncthreads();

    int ti = t>>3;
    int jb = (t&7)<<2;

    float p[4][16];
    #pragma unroll
    for (int e=0;e<16;e++){
        float qe = qs[ti][e];
        p[0][e]=qe*ks[jb+0][e];
        p[1][e]=qe*ks[jb+1][e];
        p[2][e]=qe*ks[jb+2][e];
        p[3][e]=qe*ks[jb+3][e];
    }
    float acc[4]={0.f,0.f,0.f,0.f};
    #pragma unroll
    for (int c=0;c<16;c++){
        float4 wa=wqk4[c][0], wb=wqk4[c][1], wc=wqk4[c][2], wd=wqk4[c][3];
        float w[16]={wa.x,wa.y,wa.z,wa.w, wb.x,wb.y,wb.z,wb.w,
                     wc.x,wc.y,wc.z,wc.w, wd.x,wd.y,wd.z,wd.w};
        float bw = qps[ti][c] + b1s[c];
        float wo = w2s[c];
        #pragma unroll
        for (int jj=0;jj<4;jj++){
            float r = bw + kps[jb+jj][c];
            #pragma unroll
            for (int e=0;e<16;e++) r = fmaf(w[e], p[jj][e], r);
            acc[jj] = fmaf(gelu_f(r), wo, acc[jj]);
        }
    }
    float b2 = b2l[0];
    size_t off = ((size_t)bh*Cn + (i0+ti))*Cn + j0 + jb;
    *(float4*)(g_S + off) = make_float4(0.25f*(acc[0]+b2), 0.25f*(acc[1]+b2),
                                        0.25f*(acc[2]+b2), 0.25f*(acc[3]+b2));
}

// softmax + A@V fused: grid (C/64, B*H), 256 threads = 64 rows x 4 d-groups
__global__ void __launch_bounds__(256) k_softav(){
    int bh=blockIdx.y, b=bh>>2, hh=bh&3;
    int i0=blockIdx.x<<6;
    int t=threadIdx.x, li=t>>2, g=t&3;
    const float* sr = g_S + ((size_t)bh*Cn + i0 + li)*Cn;

    float m = -3.0e38f;
    for (int k=0;k<Cn/16;k++){
        float4 v4 = *(const float4*)(sr + g*4 + k*16);
        m = fmaxf(m, fmaxf(fmaxf(v4.x,v4.y), fmaxf(v4.z,v4.w)));
    }
    __shared__ float red[64][4];
    red[li][g]=m; __syncthreads();
    m = fmaxf(fmaxf(red[li][0],red[li][1]), fmaxf(red[li][2],red[li][3]));

    __shared__ float vt[64][16];
    __shared__ float et[64][65];
    float a0=0.f,a1=0.f,a2=0.f,a3=0.f, sacc=0.f;

    for (int jt=0;jt<Cn/64;jt++){
        __syncthreads();
        {
            int row=t>>2, qd=t&3;
            float4 vv = *(const float4*)(g_v + ((size_t)(b*Cn) + jt*64 + row)*Dn + hh*16 + qd*4);
            *(float4*)&vt[row][qd*4]=vv;
        }
        {
            const float* sp = sr + jt*64 + g*16;
            #pragma unroll
            for (int kk=0;kk<16;kk+=4){
                float4 s4=*(const float4*)(sp+kk);
                float e0=__expf(s4.x-m), e1=__expf(s4.y-m);
                float e2=__expf(s4.z-m), e3=__expf(s4.w-m);
                et[li][g*16+kk+0]=e0; et[li][g*16+kk+1]=e1;
                et[li][g*16+kk+2]=e2; et[li][g*16+kk+3]=e3;
                sacc += (e0+e1)+(e2+e3);
            }
        }
        __syncthreads();
        #pragma unroll 4
        for (int jj=0;jj<64;jj++){
            float ev=et[li][jj];
            float4 vv=*(const float4*)&vt[jj][g*4];
            a0=fmaf(ev,vv.x,a0); a1=fmaf(ev,vv.y,a1);
            a2=fmaf(ev,vv.z,a2); a3=fmaf(ev,vv.w,a3);
        }
    }
    __syncthreads();
    red[li][g]=sacc; __syncthreads();
    float inv = 1.0f/(red[li][0]+red[li][1]+red[li][2]+red[li][3]);
    *(float4*)(g_attn + ((size_t)(b*Cn)+i0+li)*Dn + hh*16 + g*4)
        = make_float4(a0*inv,a1*inv,a2*inv,a3*inv);
}

// linear(IN->64) + residual + LN; IN=64 reads g_attn, IN=256 reads g_ff
template<int IN>
__global__ void k_lin_res_ln(const float* __restrict__ W, const float* __restrict__ bias,
                             const float* __restrict__ gamma, const float* __restrict__ beta){
    __shared__ float xs[4][IN];
    __shared__ float vals[4][64];
    __shared__ float stats[4][2];
    int r0=blockIdx.x*4, t=threadIdx.x;
    const float* src = (IN==64)? g_attn : g_ff;
    for (int i=t;i<4*IN;i+=64) xs[i/IN][i%IN] = src[r0*IN+i];
    __syncthreads();
    int o=t;
    float bb=bias[o];
    float acc[4]={bb,bb,bb,bb};
    for (int d=0;d<IN;d++){
        float w=W[o*IN+d];
        #pragma unroll
        for (int r=0;r<4;r++) acc[r]=fmaf(w,xs[r][d],acc[r]);
    }
    float val[4];
    #pragma unroll
    for (int r=0;r<4;r++){ val[r]=acc[r]+g_h[(r0+r)*Dn+o]; vals[r][o]=val[r]; }
    __syncthreads();
    int wr=t>>5, lane=t&31;
    #pragma unroll
    for (int rr2=0; rr2<2; rr2++){
        int rrow = wr*2+rr2;
        float v1=vals[rrow][lane], v2=vals[rrow][lane+32];
        float s=v1+v2, q=fmaf(v1,v1,v2*v2);
        #pragma unroll
        for (int off2=16; off2; off2>>=1){
            s += __shfl_down_sync(0xffffffffu, s, off2);
            q += __shfl_down_sync(0xffffffffu, q, off2);
        }
        if (lane==0){
            float mean=s*(1.0f/64.0f);
            float var = q*(1.0f/64.0f) - mean*mean;
            stats[rrow][0]=mean; stats[rrow][1]=rsqrtf(var+1e-5f);
        }
    }
    __syncthreads();
    float gm=gamma[o], bt=beta[o];
    #pragma unroll
    for (int r=0;r<4;r++)
        g_h[(r0+r)*Dn+o] = (val[r]-stats[r][0])*stats[r][1]*gm + bt;
}

__global__ void k_ffn1(const float* __restrict__ W, const float* __restrict__ bias){
    __shared__ float hs[4][Dn];
    int r0=blockIdx.x*4, t=threadIdx.x;
    hs[t>>6][t&63]=g_h[r0*Dn+t];
    __syncthreads();
    int o=t;
    float bb=bias[o];
    float acc[4]={bb,bb,bb,bb};
    for (int d=0;d<Dn;d++){
        float w=W[o*Dn+d];
        #pragma unroll
        for (int r=0;r<4;r++) acc[r]=fmaf(w,hs[r][d],acc[r]);
    }
    #pragma unroll
    for (int r=0;r<4;r++) g_ff[(r0+r)*FFn+o]=gelu_f(acc[r]);
}

__global__ void __launch_bounds__(256) k_readout(const float* __restrict__ tq,
        const float* __restrict__ hw, const float* __restrict__ hb, float* __restrict__ out){
    int b=blockIdx.x, t=threadIdx.x;
    __shared__ float ssm[Cn];
    __shared__ float tqs[Dn];
    __shared__ float red[256];
    __shared__ float pool[4][64];
    if (t<64) tqs[t]=tq[t];
    __syncthreads();
    for (int c=t;c<Cn;c+=256){
        const float* hr=g_h+((size_t)b*Cn+c)*Dn;
        float a=0.f;
        #pragma unroll
        for (int d=0;d<Dn;d++) a=fmaf(hr[d],tqs[d],a);
        ssm[c]=a*0.125f;
    }
    __syncthreads();
    float m=-3e38f;
    for (int c=t;c<Cn;c+=256) m=fmaxf(m,ssm[c]);
    red[t]=m; __syncthreads();
    for (int s2=128;s2;s2>>=1){ if(t<s2) red[t]=fmaxf(red[t],red[t+s2]); __syncthreads(); }
    m=red[0]; __syncthreads();
    float sacc=0.f;
    for (int c=t;c<Cn;c+=256){ float e=__expf(ssm[c]-m); ssm[c]=e; sacc+=e; }
    red[t]=sacc; __syncthreads();
    for (int s2=128;s2;s2>>=1){ if(t<s2) red[t]+=red[t+s2]; __syncthreads(); }
    float stot=red[0];
    __syncthreads();
    int dd=t&63, cg=t>>6;
    float acc=0.f;
    for (int c=cg*512; c<cg*512+512; c++)
        acc=fmaf(ssm[c], g_h[((size_t)b*Cn+c)*Dn+dd], acc);
    pool[cg][dd]=acc; __syncthreads();
    if (t<64) red[t]=(pool[0][t]+pool[1][t]+pool[2][t]+pool[3][t])/stot;
    __syncthreads();
    if (t<OUTn){
        float a=hb[t];
        #pragma unroll
        for (int d=0;d<Dn;d++) a=fmaf(red[d],hw[t*Dn+d],a);
        out[b*OUTn+t]=a;
    }
}

extern "C" void kernel_launch(void* const* d_in, const int* in_sizes, int n_in,
                              void* d_out, int out_size){
    (void)in_sizes; (void)n_in; (void)out_size;
    const float* x   =(const float*)d_in[0];
    const float* role=(const float*)d_in[1];
    const float* fw  =(const float*)d_in[2];
    const float* qw  =(const float*)d_in[3];  const float* qb =(const float*)d_in[4];
    const float* kw  =(const float*)d_in[5];  const float* kb =(const float*)d_in[6];
    const float* vw  =(const float*)d_in[7];  const float* vb =(const float*)d_in[8];
    const float* w1  =(const float*)d_in[9];  const float* b1 =(const float*)d_in[10];
    const float* w2  =(const float*)d_in[11]; const float* b2 =(const float*)d_in[12];
    const float* ow  =(const float*)d_in[13]; const float* ob =(const float*)d_in[14];
    const float* l1g =(const float*)d_in[15]; const float* l1b=(const float*)d_in[16];
    const float* f1w =(const float*)d_in[17]; const float* f1b=(const float*)d_in[18];
    const float* f2w =(const float*)d_in[19]; const float* f2b=(const float*)d_in[20];
    const float* l2g =(const float*)d_in[21]; const float* l2b=(const float*)d_in[22];
    const float* tq  =(const float*)d_in[23];
    const float* hw  =(const float*)d_in[24]; const float* hb =(const float*)d_in[25];
    float* out = (float*)d_out;

    int rows = Bn*Cn;                 // 16384
    k_binding<<<(Bn*Cn*Dn+255)/256,256>>>(x, role, fw);
    for (int l=0; l<Ln; l++){
        k_qkv  <<<rows/4,64>>>(qw+l*Dn*Dn, qb+l*Dn, kw+l*Dn*Dn, kb+l*Dn, vw+l*Dn*Dn, vb+l*Dn);
        k_phead<<<rows/4,64>>>(w1+l*16*48);
        dim3 gs(Cn/32, Cn/32, BHn);
        k_score<<<gs,256>>>(w1+l*16*48, b1+l*16, w2+l*16, b2+l);
        dim3 ga(Cn/64, BHn);
        k_softav<<<ga,256>>>();
        k_lin_res_ln<64> <<<rows/4,64>>>(ow+l*Dn*Dn, ob+l*Dn, l1g+l*Dn, l1b+l*Dn);
        k_ffn1<<<rows/4,256>>>(f1w+l*FFn*Dn, f1b+l*FFn);
        k_lin_res_ln<256><<<rows/4,64>>>(f2w+l*Dn*FFn, f2b+l*Dn, l2g+l*Dn, l2b+l*Dn);
    }
    k_readout<<<Bn,256>>>(tq, hw, hb, out);
}

// round 3
// speedup vs baseline: 1.0768x; 1.0768x over previous
#include <cuda_runtime.h>
#include <math.h>

#define Bn 8
#define Cn 2048
#define Dn 64
#define Hn 4
#define Ln 3
#define FFn 256
#define OUTn 10
#define BHn (Bn*Hn)

typedef unsigned long long u64;

__device__ float g_h   [Bn*Cn*Dn];
__device__ float g_q   [Bn*Cn*Dn];
__device__ float g_k   [Bn*Cn*Dn];
__device__ float g_v   [Bn*Cn*Dn];
__device__ float g_qp  [Bn*Cn*Dn];
__device__ float g_kp  [Bn*Cn*Dn];
__device__ float g_attn[Bn*Cn*Dn];
__device__ float g_ff  [Bn*Cn*FFn];
__device__ float g_S   [(size_t)BHn*Cn*Cn];

// ---- f32x2 packed helpers (sm_103a) ----
__device__ __forceinline__ u64 pk(float lo, float hi){
    u64 r; asm("mov.b64 %0,{%1,%2};" : "=l"(r) : "f"(lo), "f"(hi)); return r;
}
__device__ __forceinline__ void upk(u64 v, float& lo, float& hi){
    asm("mov.b64 {%0,%1},%2;" : "=f"(lo), "=f"(hi) : "l"(v));
}
__device__ __forceinline__ u64 mul2(u64 a, u64 b){
    u64 r; asm("mul.rn.f32x2 %0,%1,%2;" : "=l"(r) : "l"(a), "l"(b)); return r;
}
__device__ __forceinline__ u64 fma2(u64 a, u64 b, u64 c){
    u64 r; asm("fma.rn.f32x2 %0,%1,%2,%3;" : "=l"(r) : "l"(a), "l"(b), "l"(c)); return r;
}

__device__ __forceinline__ float gelu_f(float v){           // exact (cold paths)
    return 0.5f*v*(1.0f + erff(v*0.70710678118654752f));
}

// branch-free gelu via A&S 7.1.26 (erf abs err <= 1.5e-7)
__device__ __forceinline__ float gelu_fast(float r){
    float z  = r * 0.70710678118654752f;
    float az = fabsf(z);
    float w  = fmaf(0.3275911f, az, 1.0f);
    float t;  asm("rcp.approx.f32 %0, %1;" : "=f"(t) : "f"(w));
    float ex = __expf(-z*z);
    float s  = fmaf(1.061405429f, t, -1.453152027f);
    s = fmaf(s, t, 1.421413741f);
    s = fmaf(s, t, -0.284496736f);
    s = fmaf(s, t, 0.254829592f);
    s = s * t;
    float erfa = fmaf(-s, ex, 1.0f);
    float es   = copysignf(erfa, z);
    float hr   = 0.5f*r;
    return fmaf(hr, es, hr);
}

__global__ void k_binding(const float* __restrict__ x, const float* __restrict__ role,
                          const float* __restrict__ fw){
    int idx = blockIdx.x*blockDim.x + threadIdx.x;
    if (idx >= Bn*Cn*Dn) return;
    int dd = idx & 63;
    int bc = idx >> 6;
    int c  = bc & (Cn-1);
    float xl = log1pf(fmaxf(x[bc], 0.0f));
    g_h[idx] = role[c*Dn + dd] * gelu_f(xl * fw[dd]);
}

__global__ void k_qkv(const float* __restrict__ qw, const float* __restrict__ qb,
                      const float* __restrict__ kw, const float* __restrict__ kb,
                      const float* __restrict__ vw, const float* __restrict__ vb){
    __shared__ float hs[4][Dn];
    int r0 = blockIdx.x*4;
    int t  = threadIdx.x;
    for (int i=t; i<4*Dn; i+=64) hs[i>>6][i&63] = g_h[r0*Dn + i];
    __syncthreads();
    int o = t;
    float bq=qb[o], bk=kb[o], bv=vb[o];
    float aq[4]={bq,bq,bq,bq}, ak[4]={bk,bk,bk,bk}, av[4]={bv,bv,bv,bv};
    for (int d=0; d<Dn; d++){
        float wq=qw[o*Dn+d], wk2=kw[o*Dn+d], wv=vw[o*Dn+d];
        #pragma unroll
        for (int r=0;r<4;r++){
            float hh = hs[r][d];
            aq[r]=fmaf(wq ,hh,aq[r]);
            ak[r]=fmaf(wk2,hh,ak[r]);
            av[r]=fmaf(wv ,hh,av[r]);
        }
    }
    #pragma unroll
    for (int r=0;r<4;r++){
        g_q[(r0+r)*Dn+o]=aq[r];
        g_k[(r0+r)*Dn+o]=ak[r];
        g_v[(r0+r)*Dn+o]=av[r];
    }
}

// qp = q @ w1q.T + b1   (b1 folded here), kp = k @ w1k.T
__global__ void k_phead(const float* __restrict__ w1l, const float* __restrict__ b1l){
    __shared__ float qs[4][Dn], ks[4][Dn];
    int r0 = blockIdx.x*4;
    int t  = threadIdx.x;
    for (int i=t;i<4*Dn;i+=64){ qs[i>>6][i&63]=g_q[r0*Dn+i]; ks[i>>6][i&63]=g_k[r0*Dn+i]; }
    __syncthreads();
    int o=t, hh=o>>4, ci=o&15;
    float wq[16], wk[16];
    #pragma unroll
    for (int e=0;e<16;e++){ wq[e]=w1l[ci*48+e]; wk[e]=w1l[ci*48+16+e]; }
    float bb = b1l[ci];
    #pragma unroll
    for (int r=0;r<4;r++){
        float aq=bb, ak=0.f;
        #pragma unroll
        for (int e=0;e<16;e++){
            aq = fmaf(qs[r][hh*16+e], wq[e], aq);
            ak = fmaf(ks[r][hh*16+e], wk[e], ak);
        }
        g_qp[(r0+r)*Dn+o]=aq;
        g_kp[(r0+r)*Dn+o]=ak;
    }
}

// hot loop: grid (C/32 j, C/32 i, B*H), 256 threads = 32 i x (8 groups x 4 j)
__global__ void __launch_bounds__(256) k_score(const float* __restrict__ w1l,
                                               const float* __restrict__ w2l,
                                               const float* __restrict__ b2l){
    __shared__ u64 q2s[32][9];
    __shared__ u64 k2s[32][9];
    __shared__ __align__(16) u64 wqk2[16][8];
    __shared__ __align__(16) float qps[32][20];
    __shared__ __align__(16) float kps[32][20];
    __shared__ float w2s[16];

    int bh = blockIdx.z; int b = bh>>2; int hh = bh&3;
    int i0 = blockIdx.y<<5, j0 = blockIdx.x<<5;
    int t  = threadIdx.x;

    {
        int t2 = t & 127;
        int row = t2 >> 2, qd = t2 & 3;
        if (t < 128){
            int gidx = (b*Cn + i0 + row)*Dn + hh*16 + qd*4;
            float4 qv  = *(const float4*)(g_q  + gidx);
            float4 qpv = *(const float4*)(g_qp + gidx);
            q2s[row][qd*2+0] = pk(qv.x, qv.y);
            q2s[row][qd*2+1] = pk(qv.z, qv.w);
            *(float4*)&qps[row][qd*4] = qpv;
        } else {
            int gidx = (b*Cn + j0 + row)*Dn + hh*16 + qd*4;
            float4 kv  = *(const float4*)(g_k  + gidx);
            float4 kpv = *(const float4*)(g_kp + gidx);
            k2s[row][qd*2+0] = pk(kv.x, kv.y);
            k2s[row][qd*2+1] = pk(kv.z, kv.w);
            *(float4*)&kps[row][qd*4] = kpv;
        }
        if (t < 64){
            int ci=t>>2, q4=t&3;
            float4 wv = *(const float4*)(w1l + ci*48 + 32 + q4*4);
            wqk2[ci][q4*2+0] = pk(wv.x, wv.y);
            wqk2[ci][q4*2+1] = pk(wv.z, wv.w);
        }
        if (t < 16) w2s[t] = w2l[t];
    }
    __syncthreads();

    int ti = t>>3;
    int jb = (t&7)<<2;

    u64 q2[8], p2[4][8];
    #pragma unroll
    for (int e=0;e<8;e++) q2[e]=q2s[ti][e];
    #pragma unroll
    for (int jj=0;jj<4;jj++){
        #pragma unroll
        for (int e=0;e<8;e++) p2[jj][e] = mul2(q2[e], k2s[jb+jj][e]);
    }

    float acc[4]={0.f,0.f,0.f,0.f};
    #pragma unroll
    for (int c4=0;c4<4;c4++){
        float4 qp4 = *(float4*)&qps[ti][c4*4];
        float4 kp4[4];
        #pragma unroll
        for (int jj=0;jj<4;jj++) kp4[jj] = *(float4*)&kps[jb+jj][c4*4];
        #pragma unroll
        for (int cc=0;cc<4;cc++){
            int c = c4*4+cc;
            ulonglong2* pw = (ulonglong2*)&wqk2[c][0];
            ulonglong2 wA=pw[0], wB=pw[1], wC=pw[2], wD=pw[3];
            float w2c = w2s[c];
            float qpb = (cc==0)?qp4.x:(cc==1)?qp4.y:(cc==2)?qp4.z:qp4.w;
            #pragma unroll
            for (int jj=0;jj<4;jj++){
                u64 a = mul2(wA.x, p2[jj][0]);
                a = fma2(wA.y, p2[jj][1], a);
                a = fma2(wB.x, p2[jj][2], a);
                a = fma2(wB.y, p2[jj][3], a);
                u64 d = mul2(wC.x, p2[jj][4]);
                d = fma2(wC.y, p2[jj][5], d);
                d = fma2(wD.x, p2[jj][6], d);
                d = fma2(wD.y, p2[jj][7], d);
                float alo,ahi,dlo,dhi;
                upk(a,alo,ahi); upk(d,dlo,dhi);
                float kpv = (cc==0)?kp4[jj].x:(cc==1)?kp4[jj].y:(cc==2)?kp4[jj].z:kp4[jj].w;
                float r = ((alo+ahi)+(dlo+dhi)) + (qpb + kpv);
                acc[jj] = fmaf(gelu_fast(r), w2c, acc[jj]);
            }
        }
    }
    float b2 = __ldg(b2l);
    size_t off = ((size_t)bh*Cn + (i0+ti))*Cn + j0 + jb;
    *(float4*)(g_S + off) = make_float4(0.25f*(acc[0]+b2), 0.25f*(acc[1]+b2),
                                        0.25f*(acc[2]+b2), 0.25f*(acc[3]+b2));
}

// softmax + A@V fused: grid (C/64, B*H), 256 threads = 64 rows x 4 d-groups
__global__ void __launch_bounds__(256) k_softav(){
    int bh=blockIdx.y, b=bh>>2, hh=bh&3;
    int i0=blockIdx.x<<6;
    int t=threadIdx.x, li=t>>2, g=t&3;
    const float* sr = g_S + ((size_t)bh*Cn + i0 + li)*Cn;

    float m = -3.0e38f;
    for (int k=0;k<Cn/16;k++){
        float4 v4 = *(const float4*)(sr + g*4 + k*16);
        m = fmaxf(m, fmaxf(fmaxf(v4.x,v4.y), fmaxf(v4.z,v4.w)));
    }
    __shared__ float red[64][4];
    red[li][g]=m; __syncthreads();
    m = fmaxf(fmaxf(red[li][0],red[li][1]), fmaxf(red[li][2],red[li][3]));

    __shared__ float vt[64][16];
    __shared__ float et[64][65];
    float a0=0.f,a1=0.f,a2=0.f,a3=0.f, sacc=0.f;

    for (int jt=0;jt<Cn/64;jt++){
        __syncthreads();
        {
            int row=t>>2, qd=t&3;
            float4 vv = *(const float4*)(g_v + ((size_t)(b*Cn) + jt*64 + row)*Dn + hh*16 + qd*4);
            *(float4*)&vt[row][qd*4]=vv;
        }
        {
            const float* sp = sr + jt*64 + g*16;
            #pragma unroll
            for (int kk=0;kk<16;kk+=4){
                float4 s4=*(const float4*)(sp+kk);
                float e0=__expf(s4.x-m), e1=__expf(s4.y-m);
                float e2=__expf(s4.z-m), e3=__expf(s4.w-m);
                et[li][g*16+kk+0]=e0; et[li][g*16+kk+1]=e1;
                et[li][g*16+kk+2]=e2; et[li][g*16+kk+3]=e3;
                sacc += (e0+e1)+(e2+e3);
            }
        }
        __syncthreads();
        #pragma unroll 4
        for (int jj=0;jj<64;jj++){
            float ev=et[li][jj];
            float4 vv=*(const float4*)&vt[jj][g*4];
            a0=fmaf(ev,vv.x,a0); a1=fmaf(ev,vv.y,a1);
            a2=fmaf(ev,vv.z,a2); a3=fmaf(ev,vv.w,a3);
        }
    }
    __syncthreads();
    red[li][g]=sacc; __syncthreads();
    float inv = 1.0f/(red[li][0]+red[li][1]+red[li][2]+red[li][3]);
    *(float4*)(g_attn + ((size_t)(b*Cn)+i0+li)*Dn + hh*16 + g*4)
        = make_float4(a0*inv,a1*inv,a2*inv,a3*inv);
}

template<int IN>
__global__ void k_lin_res_ln(const float* __restrict__ W, const float* __restrict__ bias,
                             const float* __restrict__ gamma, const float* __restrict__ beta){
    __shared__ float xs[4][IN];
    __shared__ float vals[4][64];
    __shared__ float stats[4][2];
    int r0=blockIdx.x*4, t=threadIdx.x;
    const float* src = (IN==64)? g_attn : g_ff;
    for (int i=t;i<4*IN;i+=64) xs[i/IN][i%IN] = src[r0*IN+i];
    __syncthreads();
    int o=t;
    float bb=bias[o];
    float acc[4]={bb,bb,bb,bb};
    for (int d=0;d<IN;d++){
        float w=W[o*IN+d];
        #pragma unroll
        for (int r=0;r<4;r++) acc[r]=fmaf(w,xs[r][d],acc[r]);
    }
    float val[4];
    #pragma unroll
    for (int r=0;r<4;r++){ val[r]=acc[r]+g_h[(r0+r)*Dn+o]; vals[r][o]=val[r]; }
    __syncthreads();
    int wr=t>>5, lane=t&31;
    #pragma unroll
    for (int rr2=0; rr2<2; rr2++){
        int rrow = wr*2+rr2;
        float v1=vals[rrow][lane], v2=vals[rrow][lane+32];
        float s=v1+v2, q=fmaf(v1,v1,v2*v2);
        #pragma unroll
        for (int off2=16; off2; off2>>=1){
            s += __shfl_down_sync(0xffffffffu, s, off2);
            q += __shfl_down_sync(0xffffffffu, q, off2);
        }
        if (lane==0){
            float mean=s*(1.0f/64.0f);
            float var = q*(1.0f/64.0f) - mean*mean;
            stats[rrow][0]=mean; stats[rrow][1]=rsqrtf(var+1e-5f);
        }
    }
    __syncthreads();
    float gm=gamma[o], bt=beta[o];
    #pragma unroll
    for (int r=0;r<4;r++)
        g_h[(r0+r)*Dn+o] = (val[r]-stats[r][0])*stats[r][1]*gm + bt;
}

__global__ void k_ffn1(const float* __restrict__ W, const float* __restrict__ bias){
    __shared__ float hs[4][Dn];
    int r0=blockIdx.x*4, t=threadIdx.x;
    hs[t>>6][t&63]=g_h[r0*Dn+t];
    __syncthreads();
    int o=t;
    float bb=bias[o];
    float acc[4]={bb,bb,bb,bb};
    for (int d=0;d<Dn;d++){
        float w=W[o*Dn+d];
        #pragma unroll
        for (int r=0;r<4;r++) acc[r]=fmaf(w,hs[r][d],acc[r]);
    }
    #pragma unroll
    for (int r=0;r<4;r++) g_ff[(r0+r)*FFn+o]=gelu_f(acc[r]);
}

__global__ void __launch_bounds__(256) k_readout(const float* __restrict__ tq,
        const float* __restrict__ hw, const float* __restrict__ hb, float* __restrict__ out){
    int b=blockIdx.x, t=threadIdx.x;
    __shared__ float ssm[Cn];
    __shared__ float tqs[Dn];
    __shared__ float red[256];
    __shared__ float pool[4][64];
    if (t<64) tqs[t]=tq[t];
    __syncthreads();
    for (int c=t;c<Cn;c+=256){
        const float* hr=g_h+((size_t)b*Cn+c)*Dn;
        float a=0.f;
        #pragma unroll
        for (int d=0;d<Dn;d++) a=fmaf(hr[d],tqs[d],a);
        ssm[c]=a*0.125f;
    }
    __syncthreads();
    float m=-3e38f;
    for (int c=t;c<Cn;c+=256) m=fmaxf(m,ssm[c]);
    red[t]=m; __syncthreads();
    for (int s2=128;s2;s2>>=1){ if(t<s2) red[t]=fmaxf(red[t],red[t+s2]); __syncthreads(); }
    m=red[0]; __syncthreads();
    float sacc=0.f;
    for (int c=t;c<Cn;c+=256){ float e=__expf(ssm[c]-m); ssm[c]=e; sacc+=e; }
    red[t]=sacc; __syncthreads();
    for (int s2=128;s2;s2>>=1){ if(t<s2) red[t]+=red[t+s2]; __syncthreads(); }
    float stot=red[0];
    __syncthreads();
    int dd=t&63, cg=t>>6;
    float acc=0.f;
    for (int c=cg*512; c<cg*512+512; c++)
        acc=fmaf(ssm[c], g_h[((size_t)b*Cn+c)*Dn+dd], acc);
    pool[cg][dd]=acc; __syncthreads();
    if (t<64) red[t]=(pool[0][t]+pool[1][t]+pool[2][t]+pool[3][t])/stot;
    __syncthreads();
    if (t<OUTn){
        float a=hb[t];
        #pragma unroll
        for (int d=0;d<Dn;d++) a=fmaf(red[d],hw[t*Dn+d],a);
        out[b*OUTn+t]=a;
    }
}

extern "C" void kernel_launch(void* const* d_in, const int* in_sizes, int n_in,
                              void* d_out, int out_size){
    (void)in_sizes; (void)n_in; (void)out_size;
    const float* x   =(const float*)d_in[0];
    const float* role=(const float*)d_in[1];
    const float* fw  =(const float*)d_in[2];
    const float* qw  =(const float*)d_in[3];  const float* qb =(const float*)d_in[4];
    const float* kw  =(const float*)d_in[5];  const float* kb =(const float*)d_in[6];
    const float* vw  =(const float*)d_in[7];  const float* vb =(const float*)d_in[8];
    const float* w1  =(const float*)d_in[9];  const float* b1 =(const float*)d_in[10];
    const float* w2  =(const float*)d_in[11]; const float* b2 =(const float*)d_in[12];
    const float* ow  =(const float*)d_in[13]; const float* ob =(const float*)d_in[14];
    const float* l1g =(const float*)d_in[15]; const float* l1b=(const float*)d_in[16];
    const float* f1w =(const float*)d_in[17]; const float* f1b=(const float*)d_in[18];
    const float* f2w =(const float*)d_in[19]; const float* f2b=(const float*)d_in[20];
    const float* l2g =(const float*)d_in[21]; const float* l2b=(const float*)d_in[22];
    const float* tq  =(const float*)d_in[23];
    const float* hw  =(const float*)d_in[24]; const float* hb =(const float*)d_in[25];
    float* out = (float*)d_out;

    int rows = Bn*Cn;
    k_binding<<<(Bn*Cn*Dn+255)/256,256>>>(x, role, fw);
    for (int l=0; l<Ln; l++){
        k_qkv  <<<rows/4,64>>>(qw+l*Dn*Dn, qb+l*Dn, kw+l*Dn*Dn, kb+l*Dn, vw+l*Dn*Dn, vb+l*Dn);
        k_phead<<<rows/4,64>>>(w1+l*16*48, b1+l*16);
        dim3 gs(Cn/32, Cn/32, BHn);
        k_score<<<gs,256>>>(w1+l*16*48, w2+l*16, b2+l);
        dim3 ga(Cn/64, BHn);
        k_softav<<<ga,256>>>();
        k_lin_res_ln<64> <<<rows/4,64>>>(ow+l*Dn*Dn, ob+l*Dn, l1g+l*Dn, l1b+l*Dn);
        k_ffn1<<<rows/4,256>>>(f1w+l*FFn*Dn, f1b+l*FFn);
        k_lin_res_ln<256><<<rows/4,64>>>(f2w+l*Dn*FFn, f2b+l*Dn, l2g+l*Dn, l2b+l*Dn);
    }
    k_readout<<<Bn,256>>>(tq, hw, hb, out);
}